// round 17
// baseline (speedup 1.0000x reference)
#include <cuda_runtime.h>
#include <stdint.h>
#include <math.h>

#define D_MODEL 1024
#define N_HEADS 16
#define HEAD_DIM 64
#define BATCH 4
#define SEQ 2048
#define M_TOTAL (BATCH * SEQ)   // 8192

// Scratch (device globals — allocation-free per harness rules)
__device__ float g_Q[BATCH * N_HEADS * SEQ * HEAD_DIM];   // [B,H,S,Dh]
__device__ float g_K[BATCH * N_HEADS * SEQ * HEAD_DIM];
__device__ float g_V[BATCH * N_HEADS * SEQ * HEAD_DIM];
__device__ float g_attn[M_TOTAL * D_MODEL];               // [B,S,D]

// ===========================================================================
// Portable tensor-core helpers (mma.sync, sm_80+ PTX — no 'a'-gated features)
// ===========================================================================
__device__ __forceinline__ uint32_t f2tf32(float x) {
    uint32_t r;
    asm("cvt.rna.tf32.f32 %0, %1;" : "=r"(r) : "f"(x));
    return r;
}

// D(16x8) += A(16x8, row) * B(8x8, col)   tf32 inputs, fp32 accumulate
__device__ __forceinline__ void mma_tf32(float c[4],
                                         uint32_t a0, uint32_t a1,
                                         uint32_t a2, uint32_t a3,
                                         uint32_t b0, uint32_t b1)
{
    asm volatile(
        "mma.sync.aligned.m16n8k8.row.col.f32.tf32.tf32.f32 "
        "{%0,%1,%2,%3}, {%4,%5,%6,%7}, {%8,%9}, {%0,%1,%2,%3};"
        : "+f"(c[0]), "+f"(c[1]), "+f"(c[2]), "+f"(c[3])
        : "r"(a0), "r"(a1), "r"(a2), "r"(a3), "r"(b0), "r"(b1));
}

__device__ __forceinline__ void mma_tf32_f(float c[4],
                                           float a0, float a1,
                                           float a2, float a3,
                                           float b0, float b1)
{
    mma_tf32(c, __float_as_uint(a0), __float_as_uint(a1),
                __float_as_uint(a2), __float_as_uint(a3),
                __float_as_uint(b0), __float_as_uint(b1));
}

// ===========================================================================
// tf32 mma.sync GEMM (unchanged from the 2697us passing kernel).
// C[m,n] = sum_k X[m,k]*W[n,k] + bias[n]
// ===========================================================================
#define PAD 36

__global__ __launch_bounds__(256) void proj_mma_kernel(
    const float* __restrict__ Xin, const float* __restrict__ W,
    const float* __restrict__ bias, float* __restrict__ Cout, int mode)
{
    __shared__ uint32_t As[128 * PAD];
    __shared__ uint32_t Bs[128 * PAD];

    const float* X = (mode == 3) ? g_attn : Xin;

    const int tid  = threadIdx.x;
    const int lane = tid & 31;
    const int wid  = tid >> 5;
    const int wm   = wid & 1;
    const int wn   = wid >> 1;
    const int m0 = blockIdx.y * 128;
    const int n0 = blockIdx.x * 128;

    const int grp = lane >> 2;
    const int qid = lane & 3;

    float acc[4][4][4];
#pragma unroll
    for (int mt = 0; mt < 4; mt++)
#pragma unroll
        for (int nt = 0; nt < 4; nt++)
#pragma unroll
            for (int e = 0; e < 4; e++) acc[mt][nt][e] = 0.0f;

    int rowi[4], c4i[4];
#pragma unroll
    for (int i = 0; i < 4; i++) {
        const int f = tid + i * 256;
        rowi[i] = f >> 3;
        c4i[i]  = (f & 7) * 4;
    }

    float4 pa[4], pb[4];
#pragma unroll
    for (int i = 0; i < 4; i++) {
        pa[i] = *(const float4*)(X + (size_t)(m0 + rowi[i]) * D_MODEL + c4i[i]);
        pb[i] = *(const float4*)(W + (size_t)(n0 + rowi[i]) * D_MODEL + c4i[i]);
    }

    for (int j = 0; j < 32; j++) {
#pragma unroll
        for (int i = 0; i < 4; i++) {
            uint4 at = make_uint4(f2tf32(pa[i].x), f2tf32(pa[i].y),
                                  f2tf32(pa[i].z), f2tf32(pa[i].w));
            uint4 bt = make_uint4(f2tf32(pb[i].x), f2tf32(pb[i].y),
                                  f2tf32(pb[i].z), f2tf32(pb[i].w));
            *(uint4*)(As + rowi[i] * PAD + c4i[i]) = at;
            *(uint4*)(Bs + rowi[i] * PAD + c4i[i]) = bt;
        }
        __syncthreads();

        if (j < 31) {
            const int k0n = (j + 1) * 32;
#pragma unroll
            for (int i = 0; i < 4; i++) {
                pa[i] = *(const float4*)(X + (size_t)(m0 + rowi[i]) * D_MODEL + k0n + c4i[i]);
                pb[i] = *(const float4*)(W + (size_t)(n0 + rowi[i]) * D_MODEL + k0n + c4i[i]);
            }
        }

#pragma unroll
        for (int ks = 0; ks < 4; ks++) {
            const int kc = ks * 8 + qid;
            uint32_t af[4][4];
#pragma unroll
            for (int mt = 0; mt < 4; mt++) {
                const int ar = (wm * 64 + mt * 16 + grp) * PAD;
                af[mt][0] = As[ar + kc];
                af[mt][1] = As[ar + 8 * PAD + kc];
                af[mt][2] = As[ar + kc + 4];
                af[mt][3] = As[ar + 8 * PAD + kc + 4];
            }
            uint32_t bf[4][2];
#pragma unroll
            for (int nt = 0; nt < 4; nt++) {
                const int br = (wn * 32 + nt * 8 + grp) * PAD;
                bf[nt][0] = Bs[br + kc];
                bf[nt][1] = Bs[br + kc + 4];
            }
#pragma unroll
            for (int mt = 0; mt < 4; mt++)
#pragma unroll
                for (int nt = 0; nt < 4; nt++)
                    mma_tf32(acc[mt][nt], af[mt][0], af[mt][1], af[mt][2],
                             af[mt][3], bf[nt][0], bf[nt][1]);
        }
        __syncthreads();
    }

    float* dst = (mode == 0) ? g_Q : (mode == 1) ? g_K : g_V;
#pragma unroll
    for (int mt = 0; mt < 4; mt++) {
#pragma unroll
        for (int nt = 0; nt < 4; nt++) {
            const int n = n0 + wn * 32 + nt * 8 + qid * 2;
            const float2 b2 = *(const float2*)(bias + n);
#pragma unroll
            for (int half = 0; half < 2; half++) {
                const int m = m0 + wm * 64 + mt * 16 + grp + half * 8;
                float2 v;
                v.x = acc[mt][nt][half * 2 + 0] + b2.x;
                v.y = acc[mt][nt][half * 2 + 1] + b2.y;
                if (mode == 3) {
                    *(float2*)(Cout + (size_t)m * D_MODEL + n) = v;
                } else {
                    const int bb = m >> 11, s = m & 2047;
                    const int h  = n >> 6,  dh = n & 63;
                    *(float2*)(dst + (((size_t)(bb * N_HEADS + h) * SEQ + s)
                                      * HEAD_DIM) + dh) = v;
                }
            }
        }
    }
}

// ===========================================================================
// Tensor-core flash attention v3 (tf32 mma.sync).
// CTA: 128 thr = 4 warps; Br=128 (32 q-rows/warp as 2 m-tiles), Bc=64.
// Numerics IDENTICAL to v2: S = (Qhi + Qlo) * tf32(K); PV plain tf32 with
// l computed from tf32-rounded P.
// Key change: 2 m-tiles/warp -> every B-fragment load (QK and PV) feeds
// 2 mma, halving B-frag crossbar traffic per output. Qhi frags in regs
// (both m-tiles), Qlo frags read from SMEM. V stored with XOR swizzle
// (d ^ 8*(c&3)) -> conflict-free PV B loads without padding.
// SMEM: Qlo[128][68] + Ps[128][68] + Khi[64][68] + Vs[64][64] = 103424 B
// -> 2 CTAs/SM. Regs ~220 under __launch_bounds__(128,2) cap of 256.
// ===========================================================================
#define AT_PAD  68
#define ATTN_TC_SMEM ((128 * AT_PAD + 128 * AT_PAD + 64 * AT_PAD + 64 * 64) * 4)

__global__ __launch_bounds__(128, 2) void attn_tc_kernel()
{
    extern __shared__ float smf[];
    float* Qlo = smf;                       // [128][68] persistent
    float* Ps  = Qlo + 128 * AT_PAD;        // [128][68] P tile (Q-hi staging temp)
    float* Khi = Ps  + 128 * AT_PAD;        // [64][68]  K tile (tf32)
    float* Vs  = Khi + 64 * AT_PAD;         // [64][64]  V tile (tf32, swizzled)

    const int tid  = threadIdx.x;
    const int warp = tid >> 5;
    const int lane = tid & 31;
    const int grp  = lane >> 2;   // 0..7
    const int qid  = lane & 3;    // 0..3
    const int bh = blockIdx.y;
    const int q0 = blockIdx.x * 128;

    const float* Qg = g_Q + (size_t)bh * SEQ * HEAD_DIM + (size_t)q0 * HEAD_DIM;
    const float* Kg = g_K + (size_t)bh * SEQ * HEAD_DIM;
    const float* Vg = g_V + (size_t)bh * SEQ * HEAD_DIM;

    // ---- stage Q (128x64): scale 1/8 (exact), split; hi->Ps(temp), lo->Qlo ----
#pragma unroll
    for (int i = 0; i < 16; i++) {
        const int f = tid + i * 128;          // 2048 float4 slots
        const int row = f >> 4, c4 = (f & 15) * 4;
        float4 q = *(const float4*)(Qg + row * 64 + c4);
        q.x *= 0.125f; q.y *= 0.125f; q.z *= 0.125f; q.w *= 0.125f;
        float4 hi, lo;
        hi.x = __uint_as_float(f2tf32(q.x)); lo.x = __uint_as_float(f2tf32(q.x - hi.x));
        hi.y = __uint_as_float(f2tf32(q.y)); lo.y = __uint_as_float(f2tf32(q.y - hi.y));
        hi.z = __uint_as_float(f2tf32(q.z)); lo.z = __uint_as_float(f2tf32(q.z - hi.z));
        hi.w = __uint_as_float(f2tf32(q.w)); lo.w = __uint_as_float(f2tf32(q.w - hi.w));
        *(float4*)(Ps  + row * AT_PAD + c4) = hi;
        *(float4*)(Qlo + row * AT_PAD + c4) = lo;
    }
    __syncthreads();

    // ---- extract Q-hi A-fragments for both m-tiles into registers ----
    int arow[2];
    arow[0] = (warp * 32 + grp) * AT_PAD;
    arow[1] = (warp * 32 + 16 + grp) * AT_PAD;

    float qh[2][8][4];
#pragma unroll
    for (int mt = 0; mt < 2; mt++)
#pragma unroll
        for (int ks = 0; ks < 8; ks++) {
            const int kc = ks * 8 + qid;
            qh[mt][ks][0] = Ps[arow[mt] + kc];
            qh[mt][ks][1] = Ps[arow[mt] + 8 * AT_PAD + kc];
            qh[mt][ks][2] = Ps[arow[mt] + kc + 4];
            qh[mt][ks][3] = Ps[arow[mt] + 8 * AT_PAD + kc + 4];
        }
    __syncthreads();   // all warps done reading Ps-as-Qhi before tile 0 writes

    float m_run[2][2], l_run[2][2];
#pragma unroll
    for (int mt = 0; mt < 2; mt++) {
        m_run[mt][0] = m_run[mt][1] = -1e30f;
        l_run[mt][0] = l_run[mt][1] = 0.0f;
    }
    float oacc[2][8][4];
#pragma unroll
    for (int mt = 0; mt < 2; mt++)
#pragma unroll
        for (int nt = 0; nt < 8; nt++)
#pragma unroll
            for (int e = 0; e < 4; e++) oacc[mt][nt][e] = 0.0f;

    for (int kt = 0; kt < SEQ / 64; kt++) {
        // ---- K batch: gmem -> regs -> smem (tf32) ----
        float4 st[8];
#pragma unroll
        for (int i = 0; i < 8; i++) {
            const int f = tid + i * 128;          // 1024 slots (64x64/4)
            const int row = f >> 4, c4 = (f & 15) * 4;
            st[i] = *(const float4*)(Kg + (size_t)(kt * 64 + row) * 64 + c4);
        }
        __syncthreads();   // prev tile's Khi/Vs consumers done
#pragma unroll
        for (int i = 0; i < 8; i++) {
            const int f = tid + i * 128;
            const int row = f >> 4, c4 = (f & 15) * 4;
            float4 t;
            t.x = __uint_as_float(f2tf32(st[i].x));
            t.y = __uint_as_float(f2tf32(st[i].y));
            t.z = __uint_as_float(f2tf32(st[i].z));
            t.w = __uint_as_float(f2tf32(st[i].w));
            *(float4*)(Khi + row * AT_PAD + c4) = t;
        }
        // ---- V batch (XOR-swizzled store: col c4 ^ 8*(row&3)) ----
#pragma unroll
        for (int i = 0; i < 8; i++) {
            const int f = tid + i * 128;
            const int row = f >> 4, c4 = (f & 15) * 4;
            st[i] = *(const float4*)(Vg + (size_t)(kt * 64 + row) * 64 + c4);
        }
#pragma unroll
        for (int i = 0; i < 8; i++) {
            const int f = tid + i * 128;
            const int row = f >> 4, c4 = (f & 15) * 4;
            float4 t;
            t.x = __uint_as_float(f2tf32(st[i].x));
            t.y = __uint_as_float(f2tf32(st[i].y));
            t.z = __uint_as_float(f2tf32(st[i].z));
            t.w = __uint_as_float(f2tf32(st[i].w));
            *(float4*)(Vs + row * 64 + (c4 ^ (8 * (row & 3)))) = t;
        }
        __syncthreads();

        // ---- S = (Qhi + Qlo) K^T for both m-tiles ----
        float sacc[2][8][4];
#pragma unroll
        for (int mt = 0; mt < 2; mt++)
#pragma unroll
            for (int nt = 0; nt < 8; nt++)
#pragma unroll
                for (int e = 0; e < 4; e++) sacc[mt][nt][e] = 0.0f;

#pragma unroll
        for (int ks = 0; ks < 8; ks++) {
            const int kc = ks * 8 + qid;
            float ql[2][4];
#pragma unroll
            for (int mt = 0; mt < 2; mt++) {
                ql[mt][0] = Qlo[arow[mt] + kc];
                ql[mt][1] = Qlo[arow[mt] + 8 * AT_PAD + kc];
                ql[mt][2] = Qlo[arow[mt] + kc + 4];
                ql[mt][3] = Qlo[arow[mt] + 8 * AT_PAD + kc + 4];
            }
#pragma unroll
            for (int nt = 0; nt < 8; nt++) {
                const int br = (nt * 8 + grp) * AT_PAD;
                const float bh0 = Khi[br + kc], bh1 = Khi[br + kc + 4];
#pragma unroll
                for (int mt = 0; mt < 2; mt++) {
                    mma_tf32_f(sacc[mt][nt], ql[mt][0], ql[mt][1], ql[mt][2],
                               ql[mt][3], bh0, bh1);
                    mma_tf32_f(sacc[mt][nt], qh[mt][ks][0], qh[mt][ks][1],
                               qh[mt][ks][2], qh[mt][ks][3], bh0, bh1);
                }
            }
        }

        // ---- online softmax per m-tile (rows grp, grp+8) ----
#pragma unroll
        for (int mt = 0; mt < 2; mt++) {
            float mx0 = -1e30f, mx1 = -1e30f;
#pragma unroll
            for (int nt = 0; nt < 8; nt++) {
                mx0 = fmaxf(mx0, fmaxf(sacc[mt][nt][0], sacc[mt][nt][1]));
                mx1 = fmaxf(mx1, fmaxf(sacc[mt][nt][2], sacc[mt][nt][3]));
            }
            mx0 = fmaxf(mx0, __shfl_xor_sync(0xffffffffu, mx0, 1));
            mx0 = fmaxf(mx0, __shfl_xor_sync(0xffffffffu, mx0, 2));
            mx1 = fmaxf(mx1, __shfl_xor_sync(0xffffffffu, mx1, 1));
            mx1 = fmaxf(mx1, __shfl_xor_sync(0xffffffffu, mx1, 2));

            const float mn0 = fmaxf(m_run[mt][0], mx0);
            const float mn1 = fmaxf(m_run[mt][1], mx1);
            const float alpha0 = __expf(m_run[mt][0] - mn0);
            const float alpha1 = __expf(m_run[mt][1] - mn1);
            m_run[mt][0] = mn0; m_run[mt][1] = mn1;

            float ls0 = 0.0f, ls1 = 0.0f;
#pragma unroll
            for (int nt = 0; nt < 8; nt++) {
                const float p0 = __uint_as_float(f2tf32(__expf(sacc[mt][nt][0] - mn0)));
                const float p1 = __uint_as_float(f2tf32(__expf(sacc[mt][nt][1] - mn0)));
                const float p2 = __uint_as_float(f2tf32(__expf(sacc[mt][nt][2] - mn1)));
                const float p3 = __uint_as_float(f2tf32(__expf(sacc[mt][nt][3] - mn1)));
                ls0 += p0 + p1;
                ls1 += p2 + p3;
                *(float2*)(Ps + arow[mt] + nt * 8 + 2 * qid)              = make_float2(p0, p1);
                *(float2*)(Ps + arow[mt] + 8 * AT_PAD + nt * 8 + 2 * qid) = make_float2(p2, p3);
            }
            ls0 += __shfl_xor_sync(0xffffffffu, ls0, 1);
            ls0 += __shfl_xor_sync(0xffffffffu, ls0, 2);
            ls1 += __shfl_xor_sync(0xffffffffu, ls1, 1);
            ls1 += __shfl_xor_sync(0xffffffffu, ls1, 2);
            l_run[mt][0] = l_run[mt][0] * alpha0 + ls0;
            l_run[mt][1] = l_run[mt][1] * alpha1 + ls1;

#pragma unroll
            for (int nt = 0; nt < 8; nt++) {
                oacc[mt][nt][0] *= alpha0; oacc[mt][nt][1] *= alpha0;
                oacc[mt][nt][2] *= alpha1; oacc[mt][nt][3] *= alpha1;
            }
        }
        __syncwarp();   // Ps rows are warp-private; order stores before loads

        // ---- O += P V (V loads swizzled, conflict-free) ----
#pragma unroll
        for (int ks = 0; ks < 8; ks++) {
            const int kc = ks * 8 + qid;
            float a[2][4];
#pragma unroll
            for (int mt = 0; mt < 2; mt++) {
                a[mt][0] = Ps[arow[mt] + kc];
                a[mt][1] = Ps[arow[mt] + 8 * AT_PAD + kc];
                a[mt][2] = Ps[arow[mt] + kc + 4];
                a[mt][3] = Ps[arow[mt] + 8 * AT_PAD + kc + 4];
            }
            const int sw = 8 * qid;           // 8*(c&3), c = ks*8+qid
#pragma unroll
            for (int nt = 0; nt < 8; nt++) {
                const int d = nt * 8 + grp;
                const float b0 = Vs[(ks * 8 + qid) * 64 + (d ^ sw)];
                const float b1 = Vs[(ks * 8 + qid + 4) * 64 + (d ^ sw)];
#pragma unroll
                for (int mt = 0; mt < 2; mt++)
                    mma_tf32_f(oacc[mt][nt], a[mt][0], a[mt][1], a[mt][2],
                               a[mt][3], b0, b1);
            }
        }
    }

    // ---- epilogue: normalize, scatter into [B,S,D] ----
    const int b = bh >> 4, h = bh & 15;
#pragma unroll
    for (int mt = 0; mt < 2; mt++) {
        const float inv0 = 1.0f / l_run[mt][0];
        const float inv1 = 1.0f / l_run[mt][1];
        const int row0 = q0 + warp * 32 + mt * 16 + grp;
        const int row1 = row0 + 8;
        float* o0 = g_attn + ((size_t)(b * SEQ + row0)) * D_MODEL + h * HEAD_DIM;
        float* o1 = g_attn + ((size_t)(b * SEQ + row1)) * D_MODEL + h * HEAD_DIM;
#pragma unroll
        for (int nt = 0; nt < 8; nt++) {
            const int d = nt * 8 + 2 * qid;
            *(float2*)(o0 + d) = make_float2(oacc[mt][nt][0] * inv0,
                                             oacc[mt][nt][1] * inv0);
            *(float2*)(o1 + d) = make_float2(oacc[mt][nt][2] * inv1,
                                             oacc[mt][nt][3] * inv1);
        }
    }
}

// ---------------------------------------------------------------------------
extern "C" void kernel_launch(void* const* d_in, const int* in_sizes, int n_in,
                              void* d_out, int out_size)
{
    (void)in_sizes; (void)n_in; (void)out_size;
    const float* query = (const float*)d_in[0];
    const float* key   = (const float*)d_in[1];
    const float* value = (const float*)d_in[2];
    const float* Wq    = (const float*)d_in[3];
    const float* bq    = (const float*)d_in[4];
    const float* Wk    = (const float*)d_in[5];
    const float* bk    = (const float*)d_in[6];
    const float* Wv    = (const float*)d_in[7];
    const float* bv    = (const float*)d_in[8];
    const float* Wo    = (const float*)d_in[9];
    const float* bo    = (const float*)d_in[10];
    float* out = (float*)d_out;

    cudaFuncSetAttribute(attn_tc_kernel,
                         cudaFuncAttributeMaxDynamicSharedMemorySize,
                         ATTN_TC_SMEM);

    dim3 ggrid(D_MODEL / 128, M_TOTAL / 128);   // (8, 64)
    proj_mma_kernel<<<ggrid, 256>>>(query, Wq, bq, nullptr, 0);
    proj_mma_kernel<<<ggrid, 256>>>(key,   Wk, bk, nullptr, 1);
    proj_mma_kernel<<<ggrid, 256>>>(value, Wv, bv, nullptr, 2);

    dim3 agrid(SEQ / 128, BATCH * N_HEADS);     // (16, 64)
    attn_tc_kernel<<<agrid, 128, ATTN_TC_SMEM>>>();

    proj_mma_kernel<<<ggrid, 256>>>(nullptr, Wo, bo, out, 3);
}